// round 3
// baseline (speedup 1.0000x reference)
#include <cuda_runtime.h>
#include <cuda_bf16.h>
#include <cstdint>

#define N_NODES 100000
#define N_EDGES 1600000
#define C 128          // IN_C == HID_C == OUT_C == 128

// ---------------- device scratch (no allocations allowed) ----------------
__device__ float g_h[(size_t)N_NODES * C];   // GEMM output (h) for each layer
__device__ float g_a[(size_t)N_NODES * C];   // post-aggregation (+relu) layer-1 output
__device__ int   g_cnt[N_NODES];             // in-degree counts (excl self-loop)
__device__ int   g_cursor[N_NODES];          // CSR fill cursors
__device__ int   g_rowstart[N_NODES + 1];    // CSR row offsets
__device__ float g_inv[N_NODES];             // 1/sqrt(deg) with self-loop
__device__ int   g_esrc[N_EDGES];            // CSR: src node per slot (grouped by dst)
__device__ int   g_mode64;                   // 1 if edge_index is int64, 0 if int32

// ---------------- dtype probe ----------------
// If the buffer really is int64 indices, every sampled value is in [0, N_NODES).
// If it is int32 data misread as int64, sampled values are garbage fusions of
// two indices and land out of range with overwhelming probability.
__global__ void probe_kernel(const void* __restrict__ ei) {
    __shared__ int bad;
    if (threadIdx.x == 0) bad = 0;
    __syncthreads();
    const long long* p = (const long long*)ei;
    for (int i = threadIdx.x; i < 2048; i += blockDim.x) {
        long long v = p[i];
        if (v < 0 || v >= N_NODES) bad = 1;
    }
    __syncthreads();
    if (threadIdx.x == 0) g_mode64 = bad ? 0 : 1;
}

__device__ __forceinline__ int edge_src(const void* ei, int e) {
    if (g_mode64) return (int)((const long long*)ei)[e];
    return ((const int*)ei)[e];
}
__device__ __forceinline__ int edge_dst(const void* ei, int e) {
    if (g_mode64) return (int)((const long long*)ei)[(size_t)N_EDGES + e];
    return ((const int*)ei)[(size_t)N_EDGES + e];
}

// ---------------- CSR build kernels ----------------
__global__ void zero_kernel() {
    int i = blockIdx.x * blockDim.x + threadIdx.x;
    if (i < N_NODES) { g_cnt[i] = 0; g_cursor[i] = 0; }
}

__global__ void count_kernel(const void* __restrict__ ei) {
    int e = blockIdx.x * blockDim.x + threadIdx.x;
    if (e < N_EDGES) {
        int d = edge_dst(ei, e);
        if (d >= 0 && d < N_NODES) atomicAdd(&g_cnt[d], 1);
    }
}

__global__ void inv_kernel() {
    int i = blockIdx.x * blockDim.x + threadIdx.x;
    if (i < N_NODES) g_inv[i] = rsqrtf((float)g_cnt[i] + 1.0f);
}

// Single-block exclusive scan of g_cnt -> g_rowstart (N_NODES elements).
__global__ void scan_kernel() {
    __shared__ int warp_sums[32];
    const int tid = threadIdx.x;
    const int lane = tid & 31, wid = tid >> 5;
    int carry = 0;
    for (int base = 0; base < N_NODES; base += 1024) {
        int i = base + tid;
        int v = (i < N_NODES) ? g_cnt[i] : 0;
        int x = v;
        #pragma unroll
        for (int o = 1; o < 32; o <<= 1) {
            int t = __shfl_up_sync(0xFFFFFFFFu, x, o);
            if (lane >= o) x += t;
        }
        if (lane == 31) warp_sums[wid] = x;
        __syncthreads();
        if (wid == 0) {
            int s = warp_sums[lane];
            #pragma unroll
            for (int o = 1; o < 32; o <<= 1) {
                int t = __shfl_up_sync(0xFFFFFFFFu, s, o);
                if (lane >= o) s += t;
            }
            warp_sums[lane] = s;
        }
        __syncthreads();
        int excl_warp = (wid == 0) ? 0 : warp_sums[wid - 1];
        int incl = x + excl_warp;
        if (i < N_NODES) g_rowstart[i] = carry + incl - v;
        carry += warp_sums[31];
        __syncthreads();
    }
    if (tid == 0) g_rowstart[N_NODES] = carry;
}

__global__ void fill_kernel(const void* __restrict__ ei) {
    int e = blockIdx.x * blockDim.x + threadIdx.x;
    if (e < N_EDGES) {
        int d = edge_dst(ei, e);
        int s = edge_src(ei, e);
        if (d >= 0 && d < N_NODES && s >= 0 && s < N_NODES) {
            int pos = g_rowstart[d] + atomicAdd(&g_cursor[d], 1);
            if (pos >= 0 && pos < N_EDGES) g_esrc[pos] = s;
        }
    }
}

// ---------------- SGEMM: g_h[M,128] = A[M,128] @ W[128,128] ----------------
#define BM 64
#define BK 32
template <bool FROM_GA>
__global__ __launch_bounds__(256) void gemm128(const float* __restrict__ Aext,
                                               const float* __restrict__ W) {
    const float* __restrict__ A = FROM_GA ? g_a : Aext;
    __shared__ float Xs[BM][BK];     // [row][k]
    __shared__ float Ws[BK][C];      // [k][col]
    const int tid = threadIdx.x;
    const int tx = tid & 31;         // col group: cols tx*4 .. tx*4+3
    const int ty = tid >> 5;         // row group: rows ty*8 .. ty*8+7
    const int m0 = blockIdx.x * BM;

    float acc[8][4];
    #pragma unroll
    for (int r = 0; r < 8; r++)
        #pragma unroll
        for (int c = 0; c < 4; c++) acc[r][c] = 0.f;

    for (int kk = 0; kk < C; kk += BK) {
        #pragma unroll
        for (int l = 0; l < 2; l++) {
            int slot = tid + l * 256;
            int row = slot >> 3;
            int kg = slot & 7;
            float4 v = make_float4(0.f, 0.f, 0.f, 0.f);
            int gr = m0 + row;
            if (gr < N_NODES) v = *(const float4*)&A[(size_t)gr * C + kk + kg * 4];
            *(float4*)&Xs[row][kg * 4] = v;
        }
        #pragma unroll
        for (int l = 0; l < 4; l++) {
            int slot = tid + l * 256;
            int kr = slot >> 5;
            int cg = slot & 31;
            *(float4*)&Ws[kr][cg * 4] = *(const float4*)&W[(size_t)(kk + kr) * C + cg * 4];
        }
        __syncthreads();

        #pragma unroll
        for (int k4 = 0; k4 < BK / 4; k4++) {
            float4 b0 = *(const float4*)&Ws[k4 * 4 + 0][tx * 4];
            float4 b1 = *(const float4*)&Ws[k4 * 4 + 1][tx * 4];
            float4 b2 = *(const float4*)&Ws[k4 * 4 + 2][tx * 4];
            float4 b3 = *(const float4*)&Ws[k4 * 4 + 3][tx * 4];
            #pragma unroll
            for (int r = 0; r < 8; r++) {
                float4 a = *(const float4*)&Xs[ty * 8 + r][k4 * 4];
                acc[r][0] += a.x * b0.x + a.y * b1.x + a.z * b2.x + a.w * b3.x;
                acc[r][1] += a.x * b0.y + a.y * b1.y + a.z * b2.y + a.w * b3.y;
                acc[r][2] += a.x * b0.z + a.y * b1.z + a.z * b2.z + a.w * b3.z;
                acc[r][3] += a.x * b0.w + a.y * b1.w + a.z * b2.w + a.w * b3.w;
            }
        }
        __syncthreads();
    }

    #pragma unroll
    for (int r = 0; r < 8; r++) {
        int gr = m0 + ty * 8 + r;
        if (gr < N_NODES)
            *(float4*)&g_h[(size_t)gr * C + tx * 4] =
                make_float4(acc[r][0], acc[r][1], acc[r][2], acc[r][3]);
    }
}

// ---------------- aggregation: one warp per node, reads g_h ----------------
// out[n] = inv[n] * sum_{e in CSR(n)} inv[src]*h[src] + inv[n]^2 * h[n] + bias
template <bool TO_GA>
__global__ __launch_bounds__(256) void agg_kernel(const float* __restrict__ bias,
                                                  float* __restrict__ out) {
    int gw = (blockIdx.x * blockDim.x + threadIdx.x) >> 5;
    int lane = threadIdx.x & 31;
    if (gw >= N_NODES) return;
    const int n = gw;
    const float4* __restrict__ hv = (const float4*)g_h;

    float4 acc = make_float4(0.f, 0.f, 0.f, 0.f);
    const int e0 = g_rowstart[n];
    const int e1 = g_rowstart[n + 1];
    int e = e0;
    for (; e + 4 <= e1; e += 4) {
        int s0 = g_esrc[e + 0], s1 = g_esrc[e + 1], s2 = g_esrc[e + 2], s3 = g_esrc[e + 3];
        float w0 = g_inv[s0], w1 = g_inv[s1], w2 = g_inv[s2], w3 = g_inv[s3];
        float4 v0 = hv[(size_t)s0 * 32 + lane];
        float4 v1 = hv[(size_t)s1 * 32 + lane];
        float4 v2 = hv[(size_t)s2 * 32 + lane];
        float4 v3 = hv[(size_t)s3 * 32 + lane];
        acc.x += w0 * v0.x + w1 * v1.x + w2 * v2.x + w3 * v3.x;
        acc.y += w0 * v0.y + w1 * v1.y + w2 * v2.y + w3 * v3.y;
        acc.z += w0 * v0.z + w1 * v1.z + w2 * v2.z + w3 * v3.z;
        acc.w += w0 * v0.w + w1 * v1.w + w2 * v2.w + w3 * v3.w;
    }
    for (; e < e1; e++) {
        int s = g_esrc[e];
        float w = g_inv[s];
        float4 v = hv[(size_t)s * 32 + lane];
        acc.x += w * v.x; acc.y += w * v.y; acc.z += w * v.z; acc.w += w * v.w;
    }

    const float invd = g_inv[n];
    const float selfc = invd * invd;
    float4 hs = hv[(size_t)n * 32 + lane];
    float4 bb = ((const float4*)bias)[lane];
    float4 o;
    o.x = invd * acc.x + selfc * hs.x + bb.x;
    o.y = invd * acc.y + selfc * hs.y + bb.y;
    o.z = invd * acc.z + selfc * hs.z + bb.z;
    o.w = invd * acc.w + selfc * hs.w + bb.w;
    if (TO_GA) {
        o.x = fmaxf(o.x, 0.f); o.y = fmaxf(o.y, 0.f);
        o.z = fmaxf(o.z, 0.f); o.w = fmaxf(o.w, 0.f);
        ((float4*)g_a)[(size_t)n * 32 + lane] = o;
    } else {
        ((float4*)out)[(size_t)n * 32 + lane] = o;
    }
}

// ---------------- launch (kernel launches ONLY) ----------------
extern "C" void kernel_launch(void* const* d_in, const int* in_sizes, int n_in,
                              void* d_out, int out_size) {
    const float* x  = (const float*)d_in[0];
    const void*  ei = d_in[1];
    const float* W1 = (const float*)d_in[2];
    const float* b1 = (const float*)d_in[3];
    const float* W2 = (const float*)d_in[4];
    const float* b2 = (const float*)d_in[5];
    float* out = (float*)d_out;

    const int TB = 256;
    const int nodeBlocks = (N_NODES + TB - 1) / TB;
    const int edgeBlocks = (N_EDGES + TB - 1) / TB;
    const int gemmBlocks = (N_NODES + BM - 1) / BM;
    const int aggBlocks = (N_NODES * 32 + TB - 1) / TB;

    // dtype probe + CSR build (shared by both layers)
    probe_kernel<<<1, 256>>>(ei);
    zero_kernel<<<nodeBlocks, TB>>>();
    count_kernel<<<edgeBlocks, TB>>>(ei);
    inv_kernel<<<nodeBlocks, TB>>>();
    scan_kernel<<<1, 1024>>>();
    fill_kernel<<<edgeBlocks, TB>>>(ei);

    // layer 1: g_h = x@W1 ; g_a = relu(agg(g_h) + b1)
    gemm128<false><<<gemmBlocks, TB>>>(x, W1);
    agg_kernel<true><<<aggBlocks, TB>>>(b1, nullptr);

    // layer 2: g_h = g_a@W2 ; out = agg(g_h) + b2
    gemm128<true><<<gemmBlocks, TB>>>(nullptr, W2);
    agg_kernel<false><<<aggBlocks, TB>>>(b2, out);
}

// round 4
// speedup vs baseline: 1.2228x; 1.2228x over previous
#include <cuda_runtime.h>
#include <cuda_bf16.h>
#include <cstdint>

#define N_NODES 100000
#define N_EDGES 1600000
#define C 128          // IN_C == HID_C == OUT_C == 128

// ---------------- device scratch (no allocations allowed) ----------------
__device__ float g_h[(size_t)N_NODES * C];   // GEMM output, PRE-SCALED by inv[row]
__device__ float g_a[(size_t)N_NODES * C];   // post-aggregation (+relu) layer-1 output
__device__ int   g_cnt[N_NODES];             // in-degree counts (excl self-loop)
__device__ int   g_cursor[N_NODES];          // CSR fill cursors
__device__ int   g_rowstart[N_NODES + 1];    // CSR row offsets
__device__ float g_inv[N_NODES];             // 1/sqrt(deg) with self-loop
__device__ int   g_esrc[N_EDGES];            // CSR: src node per slot (grouped by dst)
__device__ int   g_mode64;                   // 1 if edge_index is int64, 0 if int32

// ---------------- dtype probe ----------------
__global__ void probe_kernel(const void* __restrict__ ei) {
    __shared__ int bad;
    if (threadIdx.x == 0) bad = 0;
    __syncthreads();
    const long long* p = (const long long*)ei;
    for (int i = threadIdx.x; i < 2048; i += blockDim.x) {
        long long v = p[i];
        if (v < 0 || v >= N_NODES) bad = 1;
    }
    __syncthreads();
    if (threadIdx.x == 0) g_mode64 = bad ? 0 : 1;
}

__device__ __forceinline__ int edge_src(const void* ei, int e) {
    if (g_mode64) return (int)((const long long*)ei)[e];
    return ((const int*)ei)[e];
}
__device__ __forceinline__ int edge_dst(const void* ei, int e) {
    if (g_mode64) return (int)((const long long*)ei)[(size_t)N_EDGES + e];
    return ((const int*)ei)[(size_t)N_EDGES + e];
}

// ---------------- CSR build kernels ----------------
__global__ void zero_kernel() {
    int i = blockIdx.x * blockDim.x + threadIdx.x;
    if (i < N_NODES) { g_cnt[i] = 0; g_cursor[i] = 0; }
}

__global__ void count_kernel(const void* __restrict__ ei) {
    int e = blockIdx.x * blockDim.x + threadIdx.x;
    if (e < N_EDGES) {
        int d = edge_dst(ei, e);
        if (d >= 0 && d < N_NODES) atomicAdd(&g_cnt[d], 1);
    }
}

__global__ void inv_kernel() {
    int i = blockIdx.x * blockDim.x + threadIdx.x;
    if (i < N_NODES) g_inv[i] = rsqrtf((float)g_cnt[i] + 1.0f);
}

// Chunked single-block exclusive scan: each of 1024 threads owns a contiguous
// chunk; 2 passes over global + one in-block scan (no 98-iteration barrier loop).
__global__ void scan2_kernel() {
    __shared__ int wsum[32];
    const int tid = threadIdx.x;           // 1024 threads
    const int lane = tid & 31, wid = tid >> 5;
    const int CH = (N_NODES + 1023) / 1024;  // 98
    int lo = tid * CH;
    int hi = lo + CH; if (hi > N_NODES) hi = N_NODES;
    if (lo > N_NODES) lo = N_NODES;

    int s = 0;
    for (int i = lo; i < hi; i++) s += g_cnt[i];

    int x = s;
    #pragma unroll
    for (int o = 1; o < 32; o <<= 1) {
        int t = __shfl_up_sync(0xFFFFFFFFu, x, o);
        if (lane >= o) x += t;
    }
    if (lane == 31) wsum[wid] = x;
    __syncthreads();
    if (wid == 0) {
        int w = wsum[lane];
        #pragma unroll
        for (int o = 1; o < 32; o <<= 1) {
            int t = __shfl_up_sync(0xFFFFFFFFu, w, o);
            if (lane >= o) w += t;
        }
        wsum[lane] = w;
    }
    __syncthreads();
    int base = ((wid ? wsum[wid - 1] : 0) + x - s);  // exclusive prefix of this thread
    int run = base;
    for (int i = lo; i < hi; i++) { int c = g_cnt[i]; g_rowstart[i] = run; run += c; }
    if (tid == 1023) g_rowstart[N_NODES] = run;
}

__global__ void fill_kernel(const void* __restrict__ ei) {
    int e = blockIdx.x * blockDim.x + threadIdx.x;
    if (e < N_EDGES) {
        int d = edge_dst(ei, e);
        int s = edge_src(ei, e);
        if (d >= 0 && d < N_NODES && s >= 0 && s < N_NODES) {
            int pos = g_rowstart[d] + atomicAdd(&g_cursor[d], 1);
            if (pos >= 0 && pos < N_EDGES) g_esrc[pos] = s;
        }
    }
}

// ---------------- tf32 tensor-core GEMM ----------------
// g_h[r,:] = inv[r] * (A[r,:] @ W)   (row pre-scaling fused into epilogue)
__device__ __forceinline__ float cvt_tf32(float x) {
    uint32_t u;
    asm("cvt.rna.tf32.f32 %0, %1;" : "=r"(u) : "f"(x));
    return __uint_as_float(u);
}

__device__ __forceinline__ void mma_tf32(float* c, const uint32_t* a, uint32_t b0, uint32_t b1) {
    asm volatile(
        "mma.sync.aligned.m16n8k8.row.col.f32.tf32.tf32.f32 "
        "{%0,%1,%2,%3},{%4,%5,%6,%7},{%8,%9},{%0,%1,%2,%3};"
        : "+f"(c[0]), "+f"(c[1]), "+f"(c[2]), "+f"(c[3])
        : "r"(a[0]), "r"(a[1]), "r"(a[2]), "r"(a[3]), "r"(b0), "r"(b1));
}

#define GBM 128
template <bool FROM_GA>
__global__ __launch_bounds__(256) void gemm_tf32(const float* __restrict__ Aext,
                                                 const float* __restrict__ W) {
    const float* __restrict__ A = FROM_GA ? g_a : Aext;
    __shared__ float As[GBM][36];   // 128 rows x 32 k (pad 36 -> conflict-free frag loads)
    __shared__ float Bst[C][36];    // transposed W tile: [col][k_local]

    const int tid = threadIdx.x;
    const int lane = tid & 31, wid = tid >> 5;
    const int g = lane >> 2, tig = lane & 3;
    const int rm = (wid & 3) * 32;   // warp row base (4 warps over M)
    const int cn = (wid >> 2) * 64;  // warp col base (2 warps over N)
    const int m0 = blockIdx.x * GBM;

    float acc[2][8][4] = {};

    for (int kk = 0; kk < C; kk += 32) {
        // A tile: 128x32, float4-coalesced, cvt to tf32 at fill
        #pragma unroll
        for (int l = 0; l < 4; l++) {
            int slot = tid + l * 256;          // 0..1023
            int row = slot >> 3, kg = slot & 7;
            int gr = m0 + row;
            float4 v = make_float4(0.f, 0.f, 0.f, 0.f);
            if (gr < N_NODES) v = *(const float4*)&A[(size_t)gr * C + kk + kg * 4];
            *(float4*)&As[row][kg * 4] =
                make_float4(cvt_tf32(v.x), cvt_tf32(v.y), cvt_tf32(v.z), cvt_tf32(v.w));
        }
        // W tile 32x128 stored transposed [col][k]; lanes span k -> conflict-free stores
        // (global reads are 16B-strided but W is tiny and L2-resident)
        #pragma unroll
        for (int l = 0; l < 4; l++) {
            int slot = tid + l * 256;
            int kr = slot & 31, cg = slot >> 5;
            float4 w = *(const float4*)&W[(size_t)(kk + kr) * C + cg * 4];
            Bst[cg * 4 + 0][kr] = cvt_tf32(w.x);
            Bst[cg * 4 + 1][kr] = cvt_tf32(w.y);
            Bst[cg * 4 + 2][kr] = cvt_tf32(w.z);
            Bst[cg * 4 + 3][kr] = cvt_tf32(w.w);
        }
        __syncthreads();

        #pragma unroll
        for (int k4 = 0; k4 < 4; k4++) {
            const int k = k4 * 8;
            uint32_t a[2][4];
            #pragma unroll
            for (int i = 0; i < 2; i++) {
                int r = rm + i * 16 + g;
                a[i][0] = __float_as_uint(As[r][k + tig]);
                a[i][1] = __float_as_uint(As[r + 8][k + tig]);
                a[i][2] = __float_as_uint(As[r][k + tig + 4]);
                a[i][3] = __float_as_uint(As[r + 8][k + tig + 4]);
            }
            #pragma unroll
            for (int j = 0; j < 8; j++) {
                int col = cn + j * 8 + g;
                uint32_t b0 = __float_as_uint(Bst[col][k + tig]);
                uint32_t b1 = __float_as_uint(Bst[col][k + tig + 4]);
                mma_tf32(acc[0][j], a[0], b0, b1);
                mma_tf32(acc[1][j], a[1], b0, b1);
            }
        }
        __syncthreads();
    }

    // epilogue: scale row r by g_inv[r], store to g_h
    #pragma unroll
    for (int i = 0; i < 2; i++) {
        int r0 = m0 + rm + i * 16 + g;
        int r1 = r0 + 8;
        float s0 = (r0 < N_NODES) ? g_inv[r0] : 0.f;
        float s1 = (r1 < N_NODES) ? g_inv[r1] : 0.f;
        #pragma unroll
        for (int j = 0; j < 8; j++) {
            int colb = cn + j * 8 + tig * 2;
            if (r0 < N_NODES)
                *(float2*)&g_h[(size_t)r0 * C + colb] =
                    make_float2(acc[i][j][0] * s0, acc[i][j][1] * s0);
            if (r1 < N_NODES)
                *(float2*)&g_h[(size_t)r1 * C + colb] =
                    make_float2(acc[i][j][2] * s1, acc[i][j][3] * s1);
        }
    }
}

// ---------------- aggregation: one warp per node ----------------
// g_h holds hs[r] = inv[r]*h[r]. out[n] = inv[n]*(sum_src hs[src] + hs[n]) + bias
template <bool TO_GA>
__global__ __launch_bounds__(256) void agg_kernel(const float* __restrict__ bias,
                                                  float* __restrict__ out) {
    int gw = (blockIdx.x * blockDim.x + threadIdx.x) >> 5;
    int lane = threadIdx.x & 31;
    if (gw >= N_NODES) return;
    const int n = gw;
    const float4* __restrict__ hv = (const float4*)g_h;

    float4 acc = make_float4(0.f, 0.f, 0.f, 0.f);
    const int e0 = g_rowstart[n];
    const int e1 = g_rowstart[n + 1];
    int e = e0;
    for (; e + 4 <= e1; e += 4) {
        int s0 = g_esrc[e + 0], s1 = g_esrc[e + 1], s2 = g_esrc[e + 2], s3 = g_esrc[e + 3];
        float4 v0 = hv[(size_t)s0 * 32 + lane];
        float4 v1 = hv[(size_t)s1 * 32 + lane];
        float4 v2 = hv[(size_t)s2 * 32 + lane];
        float4 v3 = hv[(size_t)s3 * 32 + lane];
        acc.x += (v0.x + v1.x) + (v2.x + v3.x);
        acc.y += (v0.y + v1.y) + (v2.y + v3.y);
        acc.z += (v0.z + v1.z) + (v2.z + v3.z);
        acc.w += (v0.w + v1.w) + (v2.w + v3.w);
    }
    for (; e < e1; e++) {
        int s = g_esrc[e];
        float4 v = hv[(size_t)s * 32 + lane];
        acc.x += v.x; acc.y += v.y; acc.z += v.z; acc.w += v.w;
    }

    const float invd = g_inv[n];
    float4 hs = hv[(size_t)n * 32 + lane];
    float4 bb = ((const float4*)bias)[lane];
    float4 o;
    o.x = invd * (acc.x + hs.x) + bb.x;
    o.y = invd * (acc.y + hs.y) + bb.y;
    o.z = invd * (acc.z + hs.z) + bb.z;
    o.w = invd * (acc.w + hs.w) + bb.w;
    if (TO_GA) {
        o.x = fmaxf(o.x, 0.f); o.y = fmaxf(o.y, 0.f);
        o.z = fmaxf(o.z, 0.f); o.w = fmaxf(o.w, 0.f);
        ((float4*)g_a)[(size_t)n * 32 + lane] = o;
    } else {
        ((float4*)out)[(size_t)n * 32 + lane] = o;
    }
}

// ---------------- launch (kernel launches ONLY) ----------------
extern "C" void kernel_launch(void* const* d_in, const int* in_sizes, int n_in,
                              void* d_out, int out_size) {
    const float* x  = (const float*)d_in[0];
    const void*  ei = d_in[1];
    const float* W1 = (const float*)d_in[2];
    const float* b1 = (const float*)d_in[3];
    const float* W2 = (const float*)d_in[4];
    const float* b2 = (const float*)d_in[5];
    float* out = (float*)d_out;

    const int TB = 256;
    const int nodeBlocks = (N_NODES + TB - 1) / TB;
    const int edgeBlocks = (N_EDGES + TB - 1) / TB;
    const int gemmBlocks = (N_NODES + GBM - 1) / GBM;
    const int aggBlocks = (N_NODES * 32 + TB - 1) / TB;

    // dtype probe + CSR build (shared by both layers)
    probe_kernel<<<1, 256>>>(ei);
    zero_kernel<<<nodeBlocks, TB>>>();
    count_kernel<<<edgeBlocks, TB>>>(ei);
    inv_kernel<<<nodeBlocks, TB>>>();
    scan2_kernel<<<1, 1024>>>();
    fill_kernel<<<edgeBlocks, TB>>>(ei);

    // layer 1: g_h = inv .* (x@W1) ; g_a = relu(agg + b1)
    gemm_tf32<false><<<gemmBlocks, TB>>>(x, W1);
    agg_kernel<true><<<aggBlocks, TB>>>(b1, nullptr);

    // layer 2: g_h = inv .* (g_a@W2) ; out = agg + b2
    gemm_tf32<true><<<gemmBlocks, TB>>>(nullptr, W2);
    agg_kernel<false><<<aggBlocks, TB>>>(b2, out);
}